// round 1
// baseline (speedup 1.0000x reference)
#include <cuda_runtime.h>
#include <cuda_bf16.h>

#define M 512
#define NW (M / 32)
#define INF_F 1e10f
#define EPS_F 1e-12f

// Deterministic scratch for per-primitive mean MST edge lengths (max 4096 primitives).
__device__ float g_mean_scratch[4096];

__global__ __launch_bounds__(M, 2) void prim_mst_kernel(
    const float* __restrict__ xyz,
    const float* __restrict__ alpha_p,
    float* __restrict__ out,
    int P, int n, int B)
{
    __shared__ float sx[M], sy[M], sz[M];
    __shared__ float s_cost[M];
    __shared__ int   s_par[M];
    __shared__ unsigned s_wval[NW], s_widx[NW];
    __shared__ unsigned s_u;
    __shared__ float s_red[NW];
    __shared__ float s_mean;

    const int tid = threadIdx.x;
    const int bp  = blockIdx.x;                 // primitive id in [0, B*P)
    const float* src = xyz + (size_t)bp * M * 3;  // primitives are contiguous: b*n + p*m == bp*m

    // Deinterleave xyz into SoA shared arrays (one-time, coalesced global reads).
    for (int i = tid; i < 3 * M; i += M) {
        float v = src[i];
        int row = i / 3, c = i - 3 * row;
        if (c == 0) sx[row] = v;
        else if (c == 1) sy[row] = v;
        else sz[row] = v;
    }
    __syncthreads();

    const float px = sx[tid], py = sy[tid], pz = sz[tid];

    // Initial best_d = D[0] row, exactly as reference: sqrt(max(sum((p_i - p_0)^2), EPS)).
    // Explicit round-to-nearest intrinsics to forbid FMA contraction (must match JAX).
    {
        // thread 0 is visited from the start; its best_d value is masked to INF anyway.
    }
    float dx = __fsub_rn(px, sx[0]);
    float dy = __fsub_rn(py, sy[0]);
    float dz = __fsub_rn(pz, sz[0]);
    float s  = __fadd_rn(__fadd_rn(__fmul_rn(dx, dx), __fmul_rn(dy, dy)), __fmul_rn(dz, dz));
    s = fmaxf(s, EPS_F);
    float best_d  = __fsqrt_rn(s);
    unsigned best_p = 0u;
    bool visited = (tid == 0);
    if (tid == 0) { s_cost[0] = 0.0f; s_par[0] = -1; }

    const unsigned INF_BITS = __float_as_uint(INF_F);
    const int lane = tid & 31;
    const int warp = tid >> 5;

    // ---- Prim's algorithm: m-1 sequential selections ----
    for (int it = 0; it < M - 1; ++it) {
        // Stage 1: per-warp argmin (value-min via REDUX, then min-index among ties).
        unsigned vb   = visited ? INF_BITS : __float_as_uint(best_d);
        unsigned wmin = __reduce_min_sync(0xffffffffu, vb);
        unsigned cidx = (vb == wmin) ? (unsigned)tid : 0xffffffffu;
        unsigned widx = __reduce_min_sync(0xffffffffu, cidx);
        if (lane == 0) { s_wval[warp] = wmin; s_widx[warp] = widx; }
        __syncthreads();

        // Stage 2: warp 0 reduces the NW per-warp winners with the same tie-break.
        if (warp == 0) {
            unsigned v2 = (lane < NW) ? s_wval[lane] : 0xffffffffu;
            unsigned i2 = (lane < NW) ? s_widx[lane] : 0xffffffffu;
            unsigned g  = __reduce_min_sync(0xffffffffu, v2);
            unsigned ci = (v2 == g) ? i2 : 0xffffffffu;
            unsigned gi = __reduce_min_sync(0xffffffffu, ci);
            if (lane == 0) s_u = gi;
        }
        __syncthreads();

        const unsigned u = s_u;
        if ((unsigned)tid == u) {
            visited = true;
            s_cost[u] = best_d;        // selected connection cost == edge length to parent
            s_par[u]  = (int)best_p;
        }

        // Relax all unvisited nodes against u (exact reference arithmetic).
        const float ux = sx[u], uy = sy[u], uz = sz[u];
        dx = __fsub_rn(px, ux);
        dy = __fsub_rn(py, uy);
        dz = __fsub_rn(pz, uz);
        s  = __fadd_rn(__fadd_rn(__fmul_rn(dx, dx), __fmul_rn(dy, dy)), __fmul_rn(dz, dz));
        s  = fmaxf(s, EPS_F);
        float d = __fsqrt_rn(s);
        if (!visited && d < best_d) { best_d = d; best_p = u; }
    }
    __syncthreads();

    // ---- Mean MST edge length over the block ----
    const float c = s_cost[tid];
    float sumv = c;
    #pragma unroll
    for (int off = 16; off; off >>= 1) sumv += __shfl_xor_sync(0xffffffffu, sumv, off);
    if (lane == 0) s_red[warp] = sumv;
    __syncthreads();
    if (warp == 0) {
        float t = (lane < NW) ? s_red[lane] : 0.0f;
        #pragma unroll
        for (int off = 16; off; off >>= 1) t += __shfl_xor_sync(0xffffffffu, t, off);
        if (lane == 0) s_mean = t / (float)(M - 1);
    }
    __syncthreads();

    const float mean  = s_mean;
    const float alpha = *alpha_p;
    const bool  mk    = c > alpha * mean;

    const int b       = bp / P;
    const int p_local = bp - b * P;
    const int base    = p_local * M;
    const size_t go   = (size_t)b * n + base + tid;

    out[go] = mk ? c : 0.0f;                                        // dist
    out[(size_t)B * n + go] = mk ? (float)(s_par[tid] + base) : -1.0f;  // assign (float-cast)
    if (tid == 0) g_mean_scratch[bp] = mean;
}

// Deterministic per-cloud mean of per-primitive means.
__global__ void mean_kernel(float* __restrict__ out, int P, int n, int B)
{
    int b = blockIdx.x * blockDim.x + threadIdx.x;
    if (b < B) {
        float s = 0.0f;
        for (int p = 0; p < P; ++p) s += g_mean_scratch[b * P + p];
        out[(size_t)2 * B * n + b] = s / (float)P;
    }
}

extern "C" void kernel_launch(void* const* d_in, const int* in_sizes, int n_in,
                              void* d_out, int out_size)
{
    const float* xyz   = (const float*)d_in[0];
    // d_in[1] = primitive_size (int, == 512, compile-time M)
    const float* alpha = (const float*)d_in[2];

    const int Bn = in_sizes[0] / 3;       // B*n = 131072
    const int B  = out_size - 2 * Bn;     // 16   (out = 2*B*n + B floats)
    const int n  = Bn / B;                // 8192
    const int P  = n / M;                 // 16
    const int nprim = B * P;              // 256

    prim_mst_kernel<<<nprim, M>>>(xyz, alpha, (float*)d_out, P, n, B);
    mean_kernel<<<1, 32>>>((float*)d_out, P, n, B);
}